// round 1
// baseline (speedup 1.0000x reference)
#include <cuda_runtime.h>
#include <math.h>

// Problem constants
#define BB   8
#define LL   3072
#define DD   1024
#define HH   16
#define EE   64
#define TOPK 8
#define NF   1537          // LL/2 + 1 (rfft length)

// ---------------------------------------------------------------------------
// Static device scratch (allocation-free rule: __device__ globals)
// ---------------------------------------------------------------------------
__device__ float  g_Qt[(size_t)BB * DD * LL];    // q projected, [B, D, L]
__device__ float  g_Kt[(size_t)BB * DD * LL];    // k projected, [B, D, L]
__device__ float  g_Vt[(size_t)BB * DD * LL];    // v projected, [B, D, L]
__device__ float  g_AggT[(size_t)BB * DD * LL];  // aggregated v, [B, D, L]
__device__ float2 g_P[(size_t)BB * DD * NF];     // per-channel spectra products
__device__ float2 g_S[BB * NF];                  // channel-reduced spectrum
__device__ float2 g_tw[LL];                      // twiddle table exp(-2*pi*i*j/L)
__device__ float  g_w[BB * TOPK];                // softmax weights
__device__ int    g_d[BB * TOPK];                // selected delays

// ---------------------------------------------------------------------------
// Twiddle init (double precision trig, 3072 entries)
// ---------------------------------------------------------------------------
__global__ void k_twiddle() {
    int j = blockIdx.x * blockDim.x + threadIdx.x;
    if (j < LL) {
        double a = -6.283185307179586476925286766559 * (double)j / (double)LL;
        g_tw[j] = make_float2((float)cos(a), (float)sin(a));
    }
}

// ---------------------------------------------------------------------------
// Projection GEMM: Ct[b, c, s] = sum_k X[b, s, k] * W[k, c] + bias[c]
// Writes TRANSPOSED [B, D, L] output so downstream FFT/gather reads rows.
// 128x128 block tile, 16 k-tile, 256 threads, 8x8 microtile.
// grid = (L/128, D/128, B)
// ---------------------------------------------------------------------------
__global__ __launch_bounds__(256) void k_proj(
    const float* __restrict__ X, const float* __restrict__ W,
    const float* __restrict__ bias, int which)
{
    __shared__ __align__(16) float As[16][128];  // As[kk][c]   = W[k0+kk][c0+c]
    __shared__ __align__(16) float Bs[16][128];  // Bs[kk][s]   = X[s0+s][k0+kk]

    float* Ct = (which == 0) ? g_Qt : (which == 1) ? g_Kt : g_Vt;

    const int b  = blockIdx.z;
    const int s0 = blockIdx.x * 128;
    const int c0 = blockIdx.y * 128;
    const float* Xb = X + (size_t)b * LL * DD;
    float* Cb = Ct + (size_t)b * DD * LL;

    const int tid = threadIdx.x;
    const int tx = tid & 15;    // n (s) microtile
    const int ty = tid >> 4;    // m (c) microtile

    float acc[8][8];
#pragma unroll
    for (int i = 0; i < 8; i++)
#pragma unroll
        for (int j = 0; j < 8; j++) acc[i][j] = 0.0f;

    for (int k0 = 0; k0 < DD; k0 += 16) {
        // Load A tile: W rows contiguous in c  (coalesced float4)
#pragma unroll
        for (int it = 0; it < 2; it++) {
            int i = tid + it * 256;          // [0, 512)
            int r  = i >> 5;                 // k row 0..15
            int c4 = i & 31;                 // float4 col 0..31
            float4 v = *(const float4*)&W[(size_t)(k0 + r) * DD + c0 + c4 * 4];
            *(float4*)&As[r][c4 * 4] = v;
        }
        // Load B tile: X rows contiguous in k (coalesced float4), transpose to smem
#pragma unroll
        for (int it = 0; it < 2; it++) {
            int i = tid + it * 256;          // [0, 512)
            int row = i >> 2;                // s row 0..127
            int c4  = i & 3;                 // k float4 0..3
            float4 v = *(const float4*)&Xb[(size_t)(s0 + row) * DD + k0 + c4 * 4];
            Bs[c4 * 4 + 0][row] = v.x;
            Bs[c4 * 4 + 1][row] = v.y;
            Bs[c4 * 4 + 2][row] = v.z;
            Bs[c4 * 4 + 3][row] = v.w;
        }
        __syncthreads();

#pragma unroll
        for (int kk = 0; kk < 16; kk++) {
            float a[8], bb[8];
            *(float4*)&a[0]  = *(const float4*)&As[kk][ty * 8];
            *(float4*)&a[4]  = *(const float4*)&As[kk][ty * 8 + 4];
            *(float4*)&bb[0] = *(const float4*)&Bs[kk][tx * 8];
            *(float4*)&bb[4] = *(const float4*)&Bs[kk][tx * 8 + 4];
#pragma unroll
            for (int i = 0; i < 8; i++)
#pragma unroll
                for (int j = 0; j < 8; j++) acc[i][j] += a[i] * bb[j];
        }
        __syncthreads();
    }

    // Epilogue: rows = channel c (stride L), cols = s contiguous
#pragma unroll
    for (int i = 0; i < 8; i++) {
        int c = c0 + ty * 8 + i;
        float bi = bias[c];
        float* dst = Cb + (size_t)c * LL + s0 + tx * 8;
        float4 v0 = make_float4(acc[i][0] + bi, acc[i][1] + bi, acc[i][2] + bi, acc[i][3] + bi);
        float4 v1 = make_float4(acc[i][4] + bi, acc[i][5] + bi, acc[i][6] + bi, acc[i][7] + bi);
        *(float4*)&dst[0] = v0;
        *(float4*)&dst[4] = v1;
    }
}

// ---------------------------------------------------------------------------
// Output GEMM: Out[b, s, n] = sum_c AggT[b, c, s] * Wo[c, n] + bo[n]
// (TN gemm: A read along m=s contiguous, B along n contiguous)
// grid = (L/128, D/128, B)
// ---------------------------------------------------------------------------
__global__ __launch_bounds__(256) void k_out(
    const float* __restrict__ Wo, const float* __restrict__ bo,
    float* __restrict__ Out)
{
    __shared__ __align__(16) float As[16][128];  // As[kk][m=s]
    __shared__ __align__(16) float Bs[16][128];  // Bs[kk][n]

    const int b  = blockIdx.z;
    const int s0 = blockIdx.x * 128;
    const int n0 = blockIdx.y * 128;
    const float* Ab = g_AggT + (size_t)b * DD * LL;

    const int tid = threadIdx.x;
    const int tx = tid & 15;   // n microtile
    const int ty = tid >> 4;   // m microtile

    float acc[8][8];
#pragma unroll
    for (int i = 0; i < 8; i++)
#pragma unroll
        for (int j = 0; j < 8; j++) acc[i][j] = 0.0f;

    for (int k0 = 0; k0 < DD; k0 += 16) {
#pragma unroll
        for (int it = 0; it < 2; it++) {
            int i = tid + it * 256;
            int r  = i >> 5;
            int c4 = i & 31;
            float4 va = *(const float4*)&Ab[(size_t)(k0 + r) * LL + s0 + c4 * 4];
            *(float4*)&As[r][c4 * 4] = va;
            float4 vb = *(const float4*)&Wo[(size_t)(k0 + r) * DD + n0 + c4 * 4];
            *(float4*)&Bs[r][c4 * 4] = vb;
        }
        __syncthreads();

#pragma unroll
        for (int kk = 0; kk < 16; kk++) {
            float a[8], bb[8];
            *(float4*)&a[0]  = *(const float4*)&As[kk][ty * 8];
            *(float4*)&a[4]  = *(const float4*)&As[kk][ty * 8 + 4];
            *(float4*)&bb[0] = *(const float4*)&Bs[kk][tx * 8];
            *(float4*)&bb[4] = *(const float4*)&Bs[kk][tx * 8 + 4];
#pragma unroll
            for (int i = 0; i < 8; i++)
#pragma unroll
                for (int j = 0; j < 8; j++) acc[i][j] += a[i] * bb[j];
        }
        __syncthreads();
    }

#pragma unroll
    for (int i = 0; i < 8; i++) {
        int s = s0 + ty * 8 + i;
        float* dst = Out + ((size_t)b * LL + s) * DD + n0 + tx * 8;
        float4 v0 = make_float4(acc[i][0] + bo[n0 + tx * 8 + 0],
                                acc[i][1] + bo[n0 + tx * 8 + 1],
                                acc[i][2] + bo[n0 + tx * 8 + 2],
                                acc[i][3] + bo[n0 + tx * 8 + 3]);
        float4 v1 = make_float4(acc[i][4] + bo[n0 + tx * 8 + 4],
                                acc[i][5] + bo[n0 + tx * 8 + 5],
                                acc[i][6] + bo[n0 + tx * 8 + 6],
                                acc[i][7] + bo[n0 + tx * 8 + 7]);
        *(float4*)&dst[0] = v0;
        *(float4*)&dst[4] = v1;
    }
}

// ---------------------------------------------------------------------------
// Mixed-radix (3 * 2^10) Stockham FFT in shared memory.
// SGN=+1: forward (exp(-i...)), SGN=-1: inverse (exp(+i...), unnormalized).
// Input in p0, ping-pongs with p1. Result ends in p1 (11 stages).
// ---------------------------------------------------------------------------
__device__ __forceinline__ float2 cmul(float2 a, float2 b) {
    return make_float2(a.x * b.x - a.y * b.y, a.x * b.y + a.y * b.x);
}

template <int SGN>
__device__ float2* block_fft(float2* p0, float2* p1, int tid, int nt)
{
    // --- radix-3 stage (n=3072, s=1, m=1024) ---
    {
        const float s0 = (SGN > 0) ? -0.86602540378443864676f
                                   :  0.86602540378443864676f;
        for (int p = tid; p < 1024; p += nt) {
            float2 a = p0[p], b = p0[p + 1024], c = p0[p + 2048];
            float ur = b.x + c.x, ui = b.y + c.y;
            float dr = b.x - c.x, di = b.y - c.y;
            float vr = a.x - 0.5f * ur, vi = a.y - 0.5f * ui;
            float wr = -s0 * di, wi = s0 * dr;      // i*s0*(b-c)
            float2 w1 = g_tw[p];       if (SGN < 0) w1.y = -w1.y;
            float2 w2 = g_tw[2 * p];   if (SGN < 0) w2.y = -w2.y;
            p1[3 * p]     = make_float2(a.x + ur, a.y + ui);
            p1[3 * p + 1] = cmul(make_float2(vr + wr, vi + wi), w1);
            p1[3 * p + 2] = cmul(make_float2(vr - wr, vi - wi), w2);
        }
    }
    __syncthreads();

    // --- ten radix-2 stages ---
    float2* px = p1;
    float2* py = p0;
    int n = 1024, s = 3;
    while (n > 1) {
        int m = n >> 1;
        int str = LL / n;                 // twiddle stride
        for (int t = tid; t < 1536; t += nt) {   // m*s == 1536 invariant
            int p = t / s;
            int q = t - p * s;
            float2 a = px[q + s * p];
            float2 b = px[q + s * (p + m)];
            float2 w = g_tw[p * str];  if (SGN < 0) w.y = -w.y;
            py[q + s * (2 * p)]     = make_float2(a.x + b.x, a.y + b.y);
            py[q + s * (2 * p + 1)] = cmul(make_float2(a.x - b.x, a.y - b.y), w);
        }
        __syncthreads();
        n = m; s <<= 1;
        float2* tp = px; px = py; py = tp;
    }
    return px;   // after 10 swaps: == p1
}

// ---------------------------------------------------------------------------
// Forward FFT of q and k rows packed as z = q + i*k (one complex FFT per
// (b, channel)); unpack via conjugate symmetry; write qhat * conj(khat).
// grid = B*D blocks, 256 threads
// ---------------------------------------------------------------------------
__global__ __launch_bounds__(256) void k_fft()
{
    __shared__ __align__(16) float2 pool[2 * LL];   // 49152 bytes
    float2* p0 = pool;
    float2* p1 = pool + LL;

    const int bc = blockIdx.x;
    const float* qr = g_Qt + (size_t)bc * LL;
    const float* kr = g_Kt + (size_t)bc * LL;
    const int tid = threadIdx.x;

    for (int i = tid; i < LL; i += 256) p0[i] = make_float2(qr[i], kr[i]);
    __syncthreads();

    float2* z = block_fft<1>(p0, p1, tid, 256);

    float2* P = g_P + (size_t)bc * NF;
    for (int f = tid; f < NF; f += 256) {
        float2 zf = z[f];
        int ridx = (f == 0) ? 0 : (LL - f);
        float2 zr = z[ridx];
        // qhat = 0.5*(zf + conj(zr)),  khat = (zf - conj(zr)) / (2i)
        float qre = 0.5f * (zf.x + zr.x);
        float qim = 0.5f * (zf.y - zr.y);
        float dr = zf.x - zr.x;
        float di = zf.y + zr.y;
        float kre = 0.5f * di;
        float kim = -0.5f * dr;
        // P = qhat * conj(khat)
        P[f] = make_float2(qre * kre + qim * kim, qim * kre - qre * kim);
    }
}

// ---------------------------------------------------------------------------
// Deterministic reduction over channels: S[b,f] = sum_c P[b,c,f]
// grid = (ceil(NF/32), B), 256 threads; coalesced over f within warps.
// ---------------------------------------------------------------------------
__global__ __launch_bounds__(256) void k_reduce()
{
    __shared__ float red[2][8][32];
    const int b    = blockIdx.y;
    const int lane = threadIdx.x & 31;
    const int cw   = threadIdx.x >> 5;          // warp 0..7
    const int f    = blockIdx.x * 32 + lane;

    float sr = 0.0f, si = 0.0f;
    if (f < NF) {
        for (int c = cw; c < DD; c += 8) {
            float2 v = g_P[((size_t)b * DD + c) * NF + f];
            sr += v.x; si += v.y;
        }
    }
    red[0][cw][lane] = sr;
    red[1][cw][lane] = si;
    __syncthreads();
    if (cw == 0 && f < NF) {
        float ar = 0.0f, ai = 0.0f;
#pragma unroll
        for (int w = 0; w < 8; w++) { ar += red[0][w][lane]; ai += red[1][w][lane]; }
        g_S[b * NF + f] = make_float2(ar, ai);
    }
}

// ---------------------------------------------------------------------------
// Per-batch inverse FFT of the reduced spectrum -> mean_value[L], then
// iterative top-8 (argmax + mask, lower-index tie break) and softmax.
// grid = B blocks, 512 threads
// ---------------------------------------------------------------------------
__global__ __launch_bounds__(512) void k_ifft_topk()
{
    __shared__ __align__(16) float2 pool[2 * LL];   // 49152 bytes, aliased below
    float2* p0 = pool;
    float2* p1 = pool + LL;

    const int b = blockIdx.x;
    const int tid = threadIdx.x;
    const int nt = 512;

    // Build full spectrum with conjugate symmetry
    for (int f = tid; f < LL; f += nt) {
        float2 v;
        if (f < NF) v = g_S[b * NF + f];
        else {
            float2 u = g_S[b * NF + (LL - f)];
            v = make_float2(u.x, -u.y);
        }
        p0[f] = v;
    }
    __syncthreads();

    float2* z = block_fft<-1>(p0, p1, tid, nt);   // z == p1

    // Aliased scratch inside pool's first half (p0 region, done being used)
    float* meanArr = (float*)pool;                 // floats [0, 3072)
    float* redV    = meanArr + 3072;               // floats [3072, 3584)
    int*   redI    = (int*)(meanArr + 3584);       // ints   [3584, 4096)

    const float scale = 1.0f / ((float)LL * (float)DD);
    for (int i = tid; i < LL; i += nt) meanArr[i] = z[i].x * scale;
    __syncthreads();

    float lw[TOPK];
    int   ld[TOPK];
    for (int k = 0; k < TOPK; k++) {
        float bv = -1e30f;
        int   bi = 0x7fffffff;
        for (int i = tid; i < LL; i += nt) {
            float v = meanArr[i];
            if (v > bv || (v == bv && i < bi)) { bv = v; bi = i; }
        }
        redV[tid] = bv; redI[tid] = bi;
        __syncthreads();
        for (int off = 256; off > 0; off >>= 1) {
            if (tid < off) {
                float v2 = redV[tid + off];
                int   i2 = redI[tid + off];
                if (v2 > redV[tid] || (v2 == redV[tid] && i2 < redI[tid])) {
                    redV[tid] = v2; redI[tid] = i2;
                }
            }
            __syncthreads();
        }
        if (tid == 0) {
            lw[k] = redV[0];
            ld[k] = redI[0];
            meanArr[redI[0]] = -1e30f;
        }
        __syncthreads();
    }

    if (tid == 0) {
        float mx = lw[0];
        for (int i = 1; i < TOPK; i++) mx = fmaxf(mx, lw[i]);
        float e[TOPK];
        float sum = 0.0f;
        for (int i = 0; i < TOPK; i++) { e[i] = expf(lw[i] - mx); sum += e[i]; }
        for (int i = 0; i < TOPK; i++) {
            g_w[b * TOPK + i] = e[i] / sum;
            g_d[b * TOPK + i] = ld[i];
        }
    }
}

// ---------------------------------------------------------------------------
// Time-delay aggregation: AggT[b,c,s] = sum_i w[b,i] * Vt[b,c,(s+d[b,i]) % L]
// grid = B*D blocks (one row each), 256 threads
// ---------------------------------------------------------------------------
__global__ __launch_bounds__(256) void k_agg()
{
    __shared__ float ws[TOPK];
    __shared__ int   ds[TOPK];
    const int bc = blockIdx.x;
    const int b  = bc >> 10;                 // / DD
    const float* vr = g_Vt + (size_t)bc * LL;
    float* orow = g_AggT + (size_t)bc * LL;
    const int tid = threadIdx.x;
    if (tid < TOPK) { ws[tid] = g_w[b * TOPK + tid]; ds[tid] = g_d[b * TOPK + tid]; }
    __syncthreads();

    for (int s = tid; s < LL; s += 256) {
        float acc = 0.0f;
#pragma unroll
        for (int i = 0; i < TOPK; i++) {
            int j = s + ds[i];
            if (j >= LL) j -= LL;
            acc += ws[i] * vr[j];
        }
        orow[s] = acc;
    }
}

// ---------------------------------------------------------------------------
// kernel_launch
// ---------------------------------------------------------------------------
extern "C" void kernel_launch(void* const* d_in, const int* in_sizes, int n_in,
                              void* d_out, int out_size)
{
    const float* queries = (const float*)d_in[0];
    const float* keys    = (const float*)d_in[1];
    const float* values  = (const float*)d_in[2];
    const float* Wq = (const float*)d_in[3];
    const float* bq = (const float*)d_in[4];
    const float* Wk = (const float*)d_in[5];
    const float* bk = (const float*)d_in[6];
    const float* Wv = (const float*)d_in[7];
    const float* bv = (const float*)d_in[8];
    const float* Wo = (const float*)d_in[9];
    const float* bo = (const float*)d_in[10];
    float* Out = (float*)d_out;

    (void)in_sizes; (void)n_in; (void)out_size;

    k_twiddle<<<(LL + 255) / 256, 256>>>();

    dim3 gg(LL / 128, DD / 128, BB);     // (24, 8, 8)
    k_proj<<<gg, 256>>>(queries, Wq, bq, 0);
    k_proj<<<gg, 256>>>(keys,    Wk, bk, 1);
    k_proj<<<gg, 256>>>(values,  Wv, bv, 2);

    k_fft<<<BB * DD, 256>>>();
    k_reduce<<<dim3((NF + 31) / 32, BB), 256>>>();
    k_ifft_topk<<<BB, 512>>>();
    k_agg<<<BB * DD, 256>>>();
    k_out<<<gg, 256>>>(Wo, bo, Out);
}

// round 3
// speedup vs baseline: 1.5428x; 1.5428x over previous
#include <cuda_runtime.h>
#include <cuda_bf16.h>
#include <math.h>
#include <stdint.h>

// Problem constants
#define BB   8
#define LL   3072
#define DD   1024
#define TOPK 8
#define NF   1537          // LL/2 + 1

#define MTOT (BB * LL)     // 24576

// ---------------------------------------------------------------------------
// Static device scratch
// ---------------------------------------------------------------------------
__device__ float  g_Qt[(size_t)BB * DD * LL];     // q projected, [B][D][L]
__device__ float  g_Kt[(size_t)BB * DD * LL];     // k projected, [B][D][L]
__device__ float  g_V [(size_t)BB * LL * DD];     // v projected, [B][L][D]
__device__ float2 g_P[(size_t)BB * DD * NF];
__device__ float2 g_S[BB * NF];
__device__ float2 g_tw[LL];
__device__ float  g_w[BB * TOPK];
__device__ int    g_d[BB * TOPK];
// bf16 hi/lo split operands
__device__ __align__(16) __nv_bfloat16 g_Ah[(size_t)MTOT * DD];
__device__ __align__(16) __nv_bfloat16 g_Al[(size_t)MTOT * DD];
__device__ __align__(16) __nv_bfloat16 g_Bh[(size_t)4 * DD * DD];  // Bw[n][k]=W[k][n]
__device__ __align__(16) __nv_bfloat16 g_Bl[(size_t)4 * DD * DD];

// ---------------------------------------------------------------------------
// PTX helpers (all base-ISA; no 'a'-suffix features)
// ---------------------------------------------------------------------------
__device__ __forceinline__ uint32_t smem_u32(const void* p) {
    uint32_t a;
    asm("{ .reg .u64 t; cvta.to.shared.u64 t, %1; cvt.u32.u64 %0, t; }"
        : "=r"(a) : "l"(p));
    return a;
}
__device__ __forceinline__ void cp16(uint32_t s, const void* g) {
    asm volatile("cp.async.cg.shared.global [%0], [%1], 16;" :: "r"(s), "l"(g));
}
__device__ __forceinline__ void cp_commit() {
    asm volatile("cp.async.commit_group;");
}
__device__ __forceinline__ void ldmx4(uint32_t* r, uint32_t a) {
    asm volatile("ldmatrix.sync.aligned.m8n8.x4.shared.b16 {%0,%1,%2,%3}, [%4];"
                 : "=r"(r[0]), "=r"(r[1]), "=r"(r[2]), "=r"(r[3]) : "r"(a));
}
__device__ __forceinline__ void mma16816(float* d, const uint32_t* a,
                                         uint32_t b0, uint32_t b1) {
    asm volatile(
        "mma.sync.aligned.m16n8k16.row.col.f32.bf16.bf16.f32 "
        "{%0,%1,%2,%3}, {%4,%5,%6,%7}, {%8,%9}, {%0,%1,%2,%3};"
        : "+f"(d[0]), "+f"(d[1]), "+f"(d[2]), "+f"(d[3])
        : "r"(a[0]), "r"(a[1]), "r"(a[2]), "r"(a[3]), "r"(b0), "r"(b1));
}

// ---------------------------------------------------------------------------
// Weight transpose + bf16 hi/lo split:  Bw[n][k] = split(W[k][n])
// ---------------------------------------------------------------------------
__global__ void k_wconv(const float* __restrict__ W0, const float* __restrict__ W1,
                        const float* __restrict__ W2, const float* __restrict__ W3)
{
    __shared__ float t[32][33];
    int z = blockIdx.z;
    const float* W = (z == 0) ? W0 : (z == 1) ? W1 : (z == 2) ? W2 : W3;
    __nv_bfloat16* Bh = g_Bh + (size_t)z * DD * DD;
    __nv_bfloat16* Bl = g_Bl + (size_t)z * DD * DD;
    int n0 = blockIdx.x * 32, k0 = blockIdx.y * 32;
    int tx = threadIdx.x, ty = threadIdx.y;
#pragma unroll
    for (int j = 0; j < 32; j += 8)
        t[ty + j][tx] = W[(size_t)(k0 + ty + j) * DD + n0 + tx];
    __syncthreads();
#pragma unroll
    for (int j = 0; j < 32; j += 8) {
        float x = t[tx][ty + j];
        __nv_bfloat16 h = __float2bfloat16(x);
        float lo = x - __bfloat162float(h);
        Bh[(size_t)(n0 + ty + j) * DD + k0 + tx] = h;
        Bl[(size_t)(n0 + ty + j) * DD + k0 + tx] = __float2bfloat16(lo);
    }
}

// ---------------------------------------------------------------------------
// A split: fp32 [M][1024] -> bf16 hi/lo
// grid = MTOT*DD/1024, 256 threads, float4 per thread
// ---------------------------------------------------------------------------
__global__ __launch_bounds__(256) void k_asplit(const float4* __restrict__ X)
{
    size_t i = (size_t)blockIdx.x * 256 + threadIdx.x;
    float4 v = X[i];
    __nv_bfloat16 h0 = __float2bfloat16(v.x), h1 = __float2bfloat16(v.y);
    __nv_bfloat16 h2 = __float2bfloat16(v.z), h3 = __float2bfloat16(v.w);
    __nv_bfloat16 l0 = __float2bfloat16(v.x - __bfloat162float(h0));
    __nv_bfloat16 l1 = __float2bfloat16(v.y - __bfloat162float(h1));
    __nv_bfloat16 l2 = __float2bfloat16(v.z - __bfloat162float(h2));
    __nv_bfloat16 l3 = __float2bfloat16(v.w - __bfloat162float(h3));
    __nv_bfloat162 ha = __halves2bfloat162(h0, h1), hb = __halves2bfloat162(h2, h3);
    __nv_bfloat162 la = __halves2bfloat162(l0, l1), lb = __halves2bfloat162(l2, l3);
    uint2 hu = make_uint2(*(uint32_t*)&ha, *(uint32_t*)&hb);
    uint2 lu = make_uint2(*(uint32_t*)&la, *(uint32_t*)&lb);
    ((uint2*)g_Ah)[i] = hu;
    ((uint2*)g_Al)[i] = lu;
}

// ---------------------------------------------------------------------------
// Tensor-core GEMM (mma.sync bf16, 3-term split):
//   C[m][n] = sum_k (Ah+Al)[m][k] * (Bh+Bl)[n][k]  + bias[n]   (AlBl dropped)
// CTA tile 128x128, k-chunk 32, cp.async double buffer, 8 warps (4m x 2n),
// warp tile 32x64.  SMEM rows are 128B: segs 0-3 = hi, 4-7 = lo, XOR-swizzled.
// modes: 0/1 -> transposed g_Qt/g_Kt, 2 -> g_V natural, 3 -> Cext natural.
// grid (DD/128, MTOT/128) = (8, 192), 256 threads.
// ---------------------------------------------------------------------------
#define KC 32
#define NC (DD / KC)       // 32 chunks
#define OFF_B 16384        // B region offset within a 32KB buffer
#define BUF_SZ 32768

__global__ __launch_bounds__(256, 2)
void k_gemm(int widx, const float* __restrict__ bias, float* __restrict__ Cext,
            int mode)
{
    extern __shared__ __align__(16) char smem[];
    __shared__ float s_bias[128];

    const int tid  = threadIdx.x;
    const int wid  = tid >> 5;
    const int lane = tid & 31;
    const int n0 = blockIdx.x * 128;
    const int m0 = blockIdx.y * 128;
    const int mw = wid >> 1;      // 0..3
    const int nw = wid & 1;       // 0..1

    const __nv_bfloat16* Bh = g_Bh + (size_t)widx * DD * DD;
    const __nv_bfloat16* Bl = g_Bl + (size_t)widx * DD * DD;

    if (tid < 128) s_bias[tid] = bias[n0 + tid];

    const uint32_t sbase = smem_u32(smem);

    float acc[2][8][4];
#pragma unroll
    for (int i = 0; i < 2; i++)
#pragma unroll
        for (int j = 0; j < 8; j++)
#pragma unroll
            for (int q = 0; q < 4; q++) acc[i][j][q] = 0.0f;

    // ---- async load of one chunk into buffer b ----
    auto load_chunk = [&](int c, int b) {
        uint32_t sb = sbase + b * BUF_SZ;
        const int k0 = c * KC;
#pragma unroll
        for (int u = 0; u < 4; u++) {
            int idx  = tid * 4 + u;          // 0..1023
            int row  = idx >> 3;
            int seg8 = idx & 7;
            int lo   = seg8 >> 2;
            int seg  = seg8 & 3;
            uint32_t so = (uint32_t)(row * 128 + ((seg8 ^ (row & 7)) * 16));
            const __nv_bfloat16* gA = (lo ? g_Al : g_Ah)
                + (size_t)(m0 + row) * DD + k0 + seg * 8;
            cp16(sb + so, gA);
            const __nv_bfloat16* gB = (lo ? Bl : Bh)
                + (size_t)(n0 + row) * DD + k0 + seg * 8;
            cp16(sb + OFF_B + so, gB);
        }
        cp_commit();
    };

    load_chunk(0, 0);

    for (int c = 0; c < NC; c++) {
        if (c + 1 < NC) {
            load_chunk(c + 1, (c + 1) & 1);
            asm volatile("cp.async.wait_group 1;");
        } else {
            asm volatile("cp.async.wait_group 0;");
        }
        __syncthreads();

        const uint32_t bufu = sbase + (c & 1) * BUF_SZ;

#pragma unroll
        for (int ks = 0; ks < 2; ks++) {
            // A fragments (hi & lo) for both m16 tiles
            uint32_t ah[2][4], al[2][4];
            const int arow0 = mw * 32 + (lane & 7) + ((lane >> 3) & 1) * 8;
            const int sega  = ks * 2 + (lane >> 4);
#pragma unroll
            for (int mi = 0; mi < 2; mi++) {
                int row = arow0 + mi * 16;
                uint32_t ra = bufu + row * 128;
                ldmx4(ah[mi], ra + ((sega       ^ (row & 7)) * 16));
                ldmx4(al[mi], ra + (((sega + 4) ^ (row & 7)) * 16));
            }
            // B fragments per n16 group, consumed immediately
            const int nrow0 = nw * 64 + ((lane >> 4) & 1) * 8 + (lane & 7);
            const int segb  = ks * 2 + ((lane >> 3) & 1);
#pragma unroll
            for (int gi = 0; gi < 4; gi++) {
                int nrow = nrow0 + gi * 16;
                uint32_t rb = bufu + OFF_B + nrow * 128;
                uint32_t bh[4], bl[4];
                ldmx4(bh, rb + ((segb       ^ (nrow & 7)) * 16));
                ldmx4(bl, rb + (((segb + 4) ^ (nrow & 7)) * 16));
#pragma unroll
                for (int half = 0; half < 2; half++) {
                    int ni = gi * 2 + half;
#pragma unroll
                    for (int mi = 0; mi < 2; mi++) {
                        mma16816(acc[mi][ni], ah[mi], bh[half * 2], bh[half * 2 + 1]);
                        mma16816(acc[mi][ni], ah[mi], bl[half * 2], bl[half * 2 + 1]);
                        mma16816(acc[mi][ni], al[mi], bh[half * 2], bh[half * 2 + 1]);
                    }
                }
            }
        }
        __syncthreads();
    }

    // ---- Epilogue: stage C tile (128 x 132 fp32) in smem, write coalesced ----
    float* smemC = (float*)smem;
#pragma unroll
    for (int mi = 0; mi < 2; mi++) {
        int r0 = mw * 32 + mi * 16 + (lane >> 2);
#pragma unroll
        for (int ni = 0; ni < 8; ni++) {
            int col = nw * 64 + ni * 8 + (lane & 3) * 2;
            smemC[r0 * 132 + col]           = acc[mi][ni][0];
            smemC[r0 * 132 + col + 1]       = acc[mi][ni][1];
            smemC[(r0 + 8) * 132 + col]     = acc[mi][ni][2];
            smemC[(r0 + 8) * 132 + col + 1] = acc[mi][ni][3];
        }
    }
    __syncthreads();

    if (mode <= 1) {
        float* dstT = (mode == 0) ? g_Qt : g_Kt;
        const int bB = m0 / LL;
        const int s0 = m0 - bB * LL;
#pragma unroll
        for (int i = 0; i < 16; i++) {
            int col = wid * 16 + i;
            float bi = s_bias[col];
            float4 o;
            o.x = smemC[(lane * 4 + 0) * 132 + col] + bi;
            o.y = smemC[(lane * 4 + 1) * 132 + col] + bi;
            o.z = smemC[(lane * 4 + 2) * 132 + col] + bi;
            o.w = smemC[(lane * 4 + 3) * 132 + col] + bi;
            *(float4*)&dstT[((size_t)bB * DD + n0 + col) * LL + s0 + lane * 4] = o;
        }
    } else {
        float* dstN = (mode == 2) ? g_V : Cext;
        const int row = tid >> 1;
        const int cb  = (tid & 1) * 64;
        const size_t rb = (size_t)(m0 + row) * DD + n0 + cb;
#pragma unroll
        for (int i = 0; i < 16; i++) {
            float4 v = *(float4*)&smemC[row * 132 + cb + i * 4];
            v.x += s_bias[cb + i * 4 + 0];
            v.y += s_bias[cb + i * 4 + 1];
            v.z += s_bias[cb + i * 4 + 2];
            v.w += s_bias[cb + i * 4 + 3];
            *(float4*)&dstN[rb + i * 4] = v;
        }
    }
}

// ---------------------------------------------------------------------------
// Twiddle init
// ---------------------------------------------------------------------------
__global__ void k_twiddle() {
    int j = blockIdx.x * blockDim.x + threadIdx.x;
    if (j < LL) {
        double a = -6.283185307179586476925286766559 * (double)j / (double)LL;
        g_tw[j] = make_float2((float)cos(a), (float)sin(a));
    }
}

// ---------------------------------------------------------------------------
// Mixed-radix (3 * 2^10) Stockham FFT in shared memory
// ---------------------------------------------------------------------------
__device__ __forceinline__ float2 cmul(float2 a, float2 b) {
    return make_float2(a.x * b.x - a.y * b.y, a.x * b.y + a.y * b.x);
}

template <int SGN>
__device__ float2* block_fft(float2* p0, float2* p1, int tid, int nt)
{
    {
        const float s0 = (SGN > 0) ? -0.86602540378443864676f
                                   :  0.86602540378443864676f;
        for (int p = tid; p < 1024; p += nt) {
            float2 a = p0[p], b = p0[p + 1024], c = p0[p + 2048];
            float ur = b.x + c.x, ui = b.y + c.y;
            float dr = b.x - c.x, di = b.y - c.y;
            float vr = a.x - 0.5f * ur, vi = a.y - 0.5f * ui;
            float wr = -s0 * di, wi = s0 * dr;
            float2 w1 = g_tw[p];       if (SGN < 0) w1.y = -w1.y;
            float2 w2 = g_tw[2 * p];   if (SGN < 0) w2.y = -w2.y;
            p1[3 * p]     = make_float2(a.x + ur, a.y + ui);
            p1[3 * p + 1] = cmul(make_float2(vr + wr, vi + wi), w1);
            p1[3 * p + 2] = cmul(make_float2(vr - wr, vi - wi), w2);
        }
    }
    __syncthreads();

    float2* px = p1;
    float2* py = p0;
    int n = 1024, s = 3;
    while (n > 1) {
        int m = n >> 1;
        int str = LL / n;
        for (int t = tid; t < 1536; t += nt) {
            int p = t / s;
            int q = t - p * s;
            float2 a = px[q + s * p];
            float2 b = px[q + s * (p + m)];
            float2 w = g_tw[p * str];  if (SGN < 0) w.y = -w.y;
            py[q + s * (2 * p)]     = make_float2(a.x + b.x, a.y + b.y);
            py[q + s * (2 * p + 1)] = cmul(make_float2(a.x - b.x, a.y - b.y), w);
        }
        __syncthreads();
        n = m; s <<= 1;
        float2* tp = px; px = py; py = tp;
    }
    return px;
}

// ---------------------------------------------------------------------------
// Forward FFT of q,k packed as z = q + i*k; write qhat * conj(khat)
// ---------------------------------------------------------------------------
__global__ __launch_bounds__(256) void k_fft()
{
    __shared__ __align__(16) float2 pool[2 * LL];
    float2* p0 = pool;
    float2* p1 = pool + LL;

    const int bc = blockIdx.x;
    const float* qr = g_Qt + (size_t)bc * LL;
    const float* kr = g_Kt + (size_t)bc * LL;
    const int tid = threadIdx.x;

    for (int i = tid; i < LL; i += 256) p0[i] = make_float2(qr[i], kr[i]);
    __syncthreads();

    float2* z = block_fft<1>(p0, p1, tid, 256);

    float2* P = g_P + (size_t)bc * NF;
    for (int f = tid; f < NF; f += 256) {
        float2 zf = z[f];
        int ridx = (f == 0) ? 0 : (LL - f);
        float2 zr = z[ridx];
        float qre = 0.5f * (zf.x + zr.x);
        float qim = 0.5f * (zf.y - zr.y);
        float dr = zf.x - zr.x;
        float di = zf.y + zr.y;
        float kre = 0.5f * di;
        float kim = -0.5f * dr;
        P[f] = make_float2(qre * kre + qim * kim, qim * kre - qre * kim);
    }
}

// ---------------------------------------------------------------------------
// Deterministic channel reduction: S[b,f] = sum_c P[b,c,f]
// ---------------------------------------------------------------------------
__global__ __launch_bounds__(256) void k_reduce()
{
    __shared__ float red[2][8][32];
    const int b    = blockIdx.y;
    const int lane = threadIdx.x & 31;
    const int cw   = threadIdx.x >> 5;
    const int f    = blockIdx.x * 32 + lane;

    float sr = 0.0f, si = 0.0f;
    if (f < NF) {
        for (int c = cw; c < DD; c += 8) {
            float2 v = g_P[((size_t)b * DD + c) * NF + f];
            sr += v.x; si += v.y;
        }
    }
    red[0][cw][lane] = sr;
    red[1][cw][lane] = si;
    __syncthreads();
    if (cw == 0 && f < NF) {
        float ar = 0.0f, ai = 0.0f;
#pragma unroll
        for (int w = 0; w < 8; w++) { ar += red[0][w][lane]; ai += red[1][w][lane]; }
        g_S[b * NF + f] = make_float2(ar, ai);
    }
}

// ---------------------------------------------------------------------------
// Per-batch inverse FFT -> mean_value, top-8 + softmax
// ---------------------------------------------------------------------------
__global__ __launch_bounds__(512) void k_ifft_topk()
{
    __shared__ __align__(16) float2 pool[2 * LL];
    float2* p0 = pool;
    float2* p1 = pool + LL;

    const int b = blockIdx.x;
    const int tid = threadIdx.x;
    const int nt = 512;

    for (int f = tid; f < LL; f += nt) {
        float2 v;
        if (f < NF) v = g_S[b * NF + f];
        else {
            float2 u = g_S[b * NF + (LL - f)];
            v = make_float2(u.x, -u.y);
        }
        p0[f] = v;
    }
    __syncthreads();

    float2* z = block_fft<-1>(p0, p1, tid, nt);

    float* meanArr = (float*)pool;
    float* redV    = meanArr + 3072;
    int*   redI    = (int*)(meanArr + 3584);

    const float scale = 1.0f / ((float)LL * (float)DD);
    for (int i = tid; i < LL; i += nt) meanArr[i] = z[i].x * scale;
    __syncthreads();

    float lw[TOPK];
    int   ld[TOPK];
    for (int k = 0; k < TOPK; k++) {
        float bv = -1e30f;
        int   bi = 0x7fffffff;
        for (int i = tid; i < LL; i += nt) {
            float v = meanArr[i];
            if (v > bv || (v == bv && i < bi)) { bv = v; bi = i; }
        }
        redV[tid] = bv; redI[tid] = bi;
        __syncthreads();
        for (int off = 256; off > 0; off >>= 1) {
            if (tid < off) {
                float v2 = redV[tid + off];
                int   i2 = redI[tid + off];
                if (v2 > redV[tid] || (v2 == redV[tid] && i2 < redI[tid])) {
                    redV[tid] = v2; redI[tid] = i2;
                }
            }
            __syncthreads();
        }
        if (tid == 0) {
            lw[k] = redV[0];
            ld[k] = redI[0];
            meanArr[redI[0]] = -1e30f;
        }
        __syncthreads();
    }

    if (tid == 0) {
        float mx = lw[0];
        for (int i = 1; i < TOPK; i++) mx = fmaxf(mx, lw[i]);
        float e[TOPK];
        float sum = 0.0f;
        for (int i = 0; i < TOPK; i++) { e[i] = expf(lw[i] - mx); sum += e[i]; }
        for (int i = 0; i < TOPK; i++) {
            g_w[b * TOPK + i] = e[i] / sum;
            g_d[b * TOPK + i] = ld[i];
        }
    }
}

// ---------------------------------------------------------------------------
// Time-delay aggregation, fused with the bf16 hi/lo split for the output GEMM:
//   agg = sum_i w[b,i] * V[b][(s+d_i)%L][c]   ->  g_Ah/g_Al
// grid (L, B), 256 threads.
// ---------------------------------------------------------------------------
__global__ __launch_bounds__(256) void k_agg()
{
    __shared__ float ws[TOPK];
    __shared__ int   ds[TOPK];
    const int s = blockIdx.x;
    const int b = blockIdx.y;
    const int tid = threadIdx.x;
    if (tid < TOPK) { ws[tid] = g_w[b * TOPK + tid]; ds[tid] = g_d[b * TOPK + tid]; }
    __syncthreads();

    const float* Vb = g_V + (size_t)b * LL * DD;
    const int c = tid * 4;
    float4 acc = make_float4(0.f, 0.f, 0.f, 0.f);
#pragma unroll
    for (int i = 0; i < TOPK; i++) {
        int j = s + ds[i];
        if (j >= LL) j -= LL;
        float4 v = *(const float4*)(Vb + (size_t)j * DD + c);
        float w = ws[i];
        acc.x += w * v.x; acc.y += w * v.y; acc.z += w * v.z; acc.w += w * v.w;
    }
    __nv_bfloat16 h0 = __float2bfloat16(acc.x), h1 = __float2bfloat16(acc.y);
    __nv_bfloat16 h2 = __float2bfloat16(acc.z), h3 = __float2bfloat16(acc.w);
    __nv_bfloat16 l0 = __float2bfloat16(acc.x - __bfloat162float(h0));
    __nv_bfloat16 l1 = __float2bfloat16(acc.y - __bfloat162float(h1));
    __nv_bfloat16 l2 = __float2bfloat16(acc.z - __bfloat162float(h2));
    __nv_bfloat16 l3 = __float2bfloat16(acc.w - __bfloat162float(h3));
    __nv_bfloat162 ha = __halves2bfloat162(h0, h1), hb = __halves2bfloat162(h2, h3);
    __nv_bfloat162 la = __halves2bfloat162(l0, l1), lb = __halves2bfloat162(l2, l3);
    size_t idx = ((size_t)b * LL + s) * DD + c;
    *(uint2*)(g_Ah + idx) = make_uint2(*(uint32_t*)&ha, *(uint32_t*)&hb);
    *(uint2*)(g_Al + idx) = make_uint2(*(uint32_t*)&la, *(uint32_t*)&lb);
}

// ---------------------------------------------------------------------------
// kernel_launch
// ---------------------------------------------------------------------------
extern "C" void kernel_launch(void* const* d_in, const int* in_sizes, int n_in,
                              void* d_out, int out_size)
{
    const float* queries = (const float*)d_in[0];
    const float* keys    = (const float*)d_in[1];
    const float* values  = (const float*)d_in[2];
    const float* Wq = (const float*)d_in[3];
    const float* bq = (const float*)d_in[4];
    const float* Wk = (const float*)d_in[5];
    const float* bk = (const float*)d_in[6];
    const float* Wv = (const float*)d_in[7];
    const float* bv = (const float*)d_in[8];
    const float* Wo = (const float*)d_in[9];
    const float* bo = (const float*)d_in[10];
    float* Out = (float*)d_out;

    (void)in_sizes; (void)n_in; (void)out_size;

    const int dynC = 128 * 132 * 4;   // 67584 (>= 2*BUF_SZ = 65536)
    static int attr_done = 0;
    if (!attr_done) {
        cudaFuncSetAttribute(k_gemm, cudaFuncAttributeMaxDynamicSharedMemorySize, dynC);
        attr_done = 1;
    }

    k_twiddle<<<(LL + 255) / 256, 256>>>();
    k_wconv<<<dim3(32, 32, 4), dim3(32, 8)>>>(Wq, Wk, Wv, Wo);

    dim3 gg(DD / 128, MTOT / 128);    // (8, 192)
    const int nsplit = (int)((size_t)MTOT * DD / 1024);   // 24576 blocks

    k_asplit<<<nsplit, 256>>>((const float4*)queries);
    k_gemm<<<gg, 256, dynC>>>(0, bq, Out, 0);
    k_asplit<<<nsplit, 256>>>((const float4*)keys);
    k_gemm<<<gg, 256, dynC>>>(1, bk, Out, 1);
    k_asplit<<<nsplit, 256>>>((const float4*)values);
    k_gemm<<<gg, 256, dynC>>>(2, bv, Out, 2);

    k_fft<<<BB * DD, 256>>>();
    k_reduce<<<dim3((NF + 31) / 32, BB), 256>>>();
    k_ifft_topk<<<BB, 512>>>();
    k_agg<<<dim3(LL, BB), 256>>>();

    k_gemm<<<gg, 256, dynC>>>(3, bo, Out, 3);
}

// round 4
// speedup vs baseline: 1.5859x; 1.0279x over previous
#include <cuda_runtime.h>
#include <cuda_bf16.h>
#include <math.h>
#include <stdint.h>

// Problem constants
#define BB   8
#define LL   3072
#define DD   1024
#define TOPK 8
#define NF   1537          // LL/2 + 1

#define MTOT (BB * LL)     // 24576

// ---------------------------------------------------------------------------
// Static device scratch
// ---------------------------------------------------------------------------
__device__ float  g_Qt[(size_t)BB * DD * LL];     // q projected, [B][D][L]
__device__ float  g_Kt[(size_t)BB * DD * LL];     // k projected, [B][D][L]
__device__ float  g_V [(size_t)BB * LL * DD];     // v projected, [B][L][D]
__device__ float2 g_P[(size_t)BB * DD * NF];
__device__ float2 g_S[BB * NF];
__device__ float2 g_tw[LL];
__device__ float  g_w[BB * TOPK];
__device__ int    g_d[BB * TOPK];
// bf16 hi/lo split A operands: 3 regions (Q,K,V); region 0 reused by k_agg
__device__ __align__(16) __nv_bfloat16 g_Ah[(size_t)3 * MTOT * DD];
__device__ __align__(16) __nv_bfloat16 g_Al[(size_t)3 * MTOT * DD];
__device__ __align__(16) __nv_bfloat16 g_Bh[(size_t)4 * DD * DD];  // Bw[n][k]=W[k][n]
__device__ __align__(16) __nv_bfloat16 g_Bl[(size_t)4 * DD * DD];

// ---------------------------------------------------------------------------
// PTX helpers (all base-ISA; no 'a'-suffix features)
// ---------------------------------------------------------------------------
__device__ __forceinline__ uint32_t smem_u32(const void* p) {
    uint32_t a;
    asm("{ .reg .u64 t; cvta.to.shared.u64 t, %1; cvt.u32.u64 %0, t; }"
        : "=r"(a) : "l"(p));
    return a;
}
__device__ __forceinline__ void cp16(uint32_t s, const void* g) {
    asm volatile("cp.async.cg.shared.global [%0], [%1], 16;" :: "r"(s), "l"(g));
}
__device__ __forceinline__ void cp_commit() {
    asm volatile("cp.async.commit_group;");
}
// NOTE: not volatile — pure data ops; lets the scheduler hoist/interleave.
__device__ __forceinline__ void ldmx4(uint32_t* r, uint32_t a) {
    asm("ldmatrix.sync.aligned.m8n8.x4.shared.b16 {%0,%1,%2,%3}, [%4];"
        : "=r"(r[0]), "=r"(r[1]), "=r"(r[2]), "=r"(r[3]) : "r"(a));
}
__device__ __forceinline__ void mma16816(float* d, const uint32_t* a,
                                         uint32_t b0, uint32_t b1) {
    asm("mma.sync.aligned.m16n8k16.row.col.f32.bf16.bf16.f32 "
        "{%0,%1,%2,%3}, {%4,%5,%6,%7}, {%8,%9}, {%0,%1,%2,%3};"
        : "+f"(d[0]), "+f"(d[1]), "+f"(d[2]), "+f"(d[3])
        : "r"(a[0]), "r"(a[1]), "r"(a[2]), "r"(a[3]), "r"(b0), "r"(b1));
}

// ---------------------------------------------------------------------------
// Weight transpose + bf16 hi/lo split:  Bw[n][k] = split(W[k][n])
// ---------------------------------------------------------------------------
__global__ void k_wconv(const float* __restrict__ W0, const float* __restrict__ W1,
                        const float* __restrict__ W2, const float* __restrict__ W3)
{
    __shared__ float t[32][33];
    int z = blockIdx.z;
    const float* W = (z == 0) ? W0 : (z == 1) ? W1 : (z == 2) ? W2 : W3;
    __nv_bfloat16* Bh = g_Bh + (size_t)z * DD * DD;
    __nv_bfloat16* Bl = g_Bl + (size_t)z * DD * DD;
    int n0 = blockIdx.x * 32, k0 = blockIdx.y * 32;
    int tx = threadIdx.x, ty = threadIdx.y;
#pragma unroll
    for (int j = 0; j < 32; j += 8)
        t[ty + j][tx] = W[(size_t)(k0 + ty + j) * DD + n0 + tx];
    __syncthreads();
#pragma unroll
    for (int j = 0; j < 32; j += 8) {
        float x = t[tx][ty + j];
        __nv_bfloat16 h = __float2bfloat16(x);
        float lo = x - __bfloat162float(h);
        Bh[(size_t)(n0 + ty + j) * DD + k0 + tx] = h;
        Bl[(size_t)(n0 + ty + j) * DD + k0 + tx] = __float2bfloat16(lo);
    }
}

// ---------------------------------------------------------------------------
// A split for Q,K,V in one launch: fp32 -> bf16 hi/lo into region blockIdx.y
// grid (MTOT*DD/1024, 3), 256 threads, float4 per thread
// ---------------------------------------------------------------------------
__global__ __launch_bounds__(256) void k_asplit3(
    const float4* __restrict__ X0, const float4* __restrict__ X1,
    const float4* __restrict__ X2)
{
    const int reg = blockIdx.y;
    const float4* X = (reg == 0) ? X0 : (reg == 1) ? X1 : X2;
    size_t i = (size_t)blockIdx.x * 256 + threadIdx.x;
    float4 v = X[i];
    __nv_bfloat16 h0 = __float2bfloat16(v.x), h1 = __float2bfloat16(v.y);
    __nv_bfloat16 h2 = __float2bfloat16(v.z), h3 = __float2bfloat16(v.w);
    __nv_bfloat16 l0 = __float2bfloat16(v.x - __bfloat162float(h0));
    __nv_bfloat16 l1 = __float2bfloat16(v.y - __bfloat162float(h1));
    __nv_bfloat16 l2 = __float2bfloat16(v.z - __bfloat162float(h2));
    __nv_bfloat16 l3 = __float2bfloat16(v.w - __bfloat162float(h3));
    __nv_bfloat162 ha = __halves2bfloat162(h0, h1), hb = __halves2bfloat162(h2, h3);
    __nv_bfloat162 la = __halves2bfloat162(l0, l1), lb = __halves2bfloat162(l2, l3);
    size_t o = (size_t)reg * (MTOT * DD / 4) + i;
    ((uint2*)g_Ah)[o] = make_uint2(*(uint32_t*)&ha, *(uint32_t*)&hb);
    ((uint2*)g_Al)[o] = make_uint2(*(uint32_t*)&la, *(uint32_t*)&lb);
}

// ---------------------------------------------------------------------------
// Tensor-core GEMM (mma.sync bf16, 3-term split):
//   C[m][n] = sum_k (Ah+Al)[m][k] * (Bh+Bl)[n][k]  + bias[n]   (AlBl dropped)
// CTA tile 128x128, k-chunk 32, cp.async TRIPLE buffer, 8 warps (4m x 2n),
// warp tile 32x64. SMEM rows 128B: segs 0-3 = hi, 4-7 = lo, XOR-swizzled.
// MMA issue is term-major per B-group: same-acc reuse distance = 4.
// modes: 0/1 -> transposed g_Qt/g_Kt, 2 -> g_V natural, 3 -> Cext natural.
// grid (DD/128, MTOT/128) = (8, 192), 256 threads.
// ---------------------------------------------------------------------------
#define KC 32
#define NC (DD / KC)       // 32 chunks
#define OFF_B 16384        // B region offset within a 32KB buffer
#define BUF_SZ 32768
#define NSTG 3

__global__ __launch_bounds__(256, 2)
void k_gemm(int areg, int widx, const float* __restrict__ bias,
            float* __restrict__ Cext, int mode)
{
    extern __shared__ __align__(16) char smem[];
    __shared__ float s_bias[128];

    const int tid  = threadIdx.x;
    const int wid  = tid >> 5;
    const int lane = tid & 31;
    const int n0 = blockIdx.x * 128;
    const int m0 = blockIdx.y * 128;
    const int mw = wid >> 1;      // 0..3
    const int nw = wid & 1;       // 0..1

    const __nv_bfloat16* Ah = g_Ah + (size_t)areg * MTOT * DD;
    const __nv_bfloat16* Al = g_Al + (size_t)areg * MTOT * DD;
    const __nv_bfloat16* Bh = g_Bh + (size_t)widx * DD * DD;
    const __nv_bfloat16* Bl = g_Bl + (size_t)widx * DD * DD;

    if (tid < 128) s_bias[tid] = bias[n0 + tid];

    const uint32_t sbase = smem_u32(smem);

    float acc[2][8][4];
#pragma unroll
    for (int i = 0; i < 2; i++)
#pragma unroll
        for (int j = 0; j < 8; j++)
#pragma unroll
            for (int q = 0; q < 4; q++) acc[i][j][q] = 0.0f;

    // ---- async load of one chunk into buffer b ----
    auto load_chunk = [&](int c, int b) {
        uint32_t sb = sbase + b * BUF_SZ;
        const int k0 = c * KC;
#pragma unroll
        for (int u = 0; u < 4; u++) {
            int idx  = tid * 4 + u;          // 0..1023
            int row  = idx >> 3;
            int seg8 = idx & 7;
            int lo   = seg8 >> 2;
            int seg  = seg8 & 3;
            uint32_t so = (uint32_t)(row * 128 + ((seg8 ^ (row & 7)) * 16));
            const __nv_bfloat16* gA = (lo ? Al : Ah)
                + (size_t)(m0 + row) * DD + k0 + seg * 8;
            cp16(sb + so, gA);
            const __nv_bfloat16* gB = (lo ? Bl : Bh)
                + (size_t)(n0 + row) * DD + k0 + seg * 8;
            cp16(sb + OFF_B + so, gB);
        }
        cp_commit();
    };

    load_chunk(0, 0);
    load_chunk(1, 1);

    int bufc = 0;   // c % 3
    for (int c = 0; c < NC; c++) {
        if (c + 2 < NC) {
            int b2 = bufc + 2; if (b2 >= NSTG) b2 -= NSTG;
            load_chunk(c + 2, b2);
            asm volatile("cp.async.wait_group 2;");
        } else if (c + 1 < NC) {
            asm volatile("cp.async.wait_group 1;");
        } else {
            asm volatile("cp.async.wait_group 0;");
        }
        __syncthreads();

        const uint32_t bufu = sbase + bufc * BUF_SZ;

#pragma unroll
        for (int ks = 0; ks < 2; ks++) {
            // A fragments (hi & lo) for both m16 tiles
            uint32_t ah[2][4], al[2][4];
            const int arow0 = mw * 32 + (lane & 7) + ((lane >> 3) & 1) * 8;
            const int sega  = ks * 2 + (lane >> 4);
#pragma unroll
            for (int mi = 0; mi < 2; mi++) {
                int row = arow0 + mi * 16;
                uint32_t ra = bufu + row * 128;
                ldmx4(ah[mi], ra + ((sega       ^ (row & 7)) * 16));
                ldmx4(al[mi], ra + (((sega + 4) ^ (row & 7)) * 16));
            }
            // B fragments per n16 group; term-major MMA issue
            const int nrow0 = nw * 64 + ((lane >> 4) & 1) * 8 + (lane & 7);
            const int segb  = ks * 2 + ((lane >> 3) & 1);
#pragma unroll
            for (int gi = 0; gi < 4; gi++) {
                int nrow = nrow0 + gi * 16;
                uint32_t rb = bufu + OFF_B + nrow * 128;
                uint32_t bh[4], bl[4];
                ldmx4(bh, rb + ((segb       ^ (nrow & 7)) * 16));
                ldmx4(bl, rb + (((segb + 4) ^ (nrow & 7)) * 16));
                // term Ah*Bh  (4 independent accumulators)
#pragma unroll
                for (int half = 0; half < 2; half++)
#pragma unroll
                    for (int mi = 0; mi < 2; mi++)
                        mma16816(acc[mi][gi * 2 + half], ah[mi],
                                 bh[half * 2], bh[half * 2 + 1]);
                // term Ah*Bl
#pragma unroll
                for (int half = 0; half < 2; half++)
#pragma unroll
                    for (int mi = 0; mi < 2; mi++)
                        mma16816(acc[mi][gi * 2 + half], ah[mi],
                                 bl[half * 2], bl[half * 2 + 1]);
                // term Al*Bh
#pragma unroll
                for (int half = 0; half < 2; half++)
#pragma unroll
                    for (int mi = 0; mi < 2; mi++)
                        mma16816(acc[mi][gi * 2 + half], al[mi],
                                 bh[half * 2], bh[half * 2 + 1]);
            }
        }
        __syncthreads();
        bufc = (bufc + 1 == NSTG) ? 0 : bufc + 1;
    }

    // ---- Epilogue: stage C tile (128 x 132 fp32) in smem, write coalesced ----
    float* smemC = (float*)smem;
#pragma unroll
    for (int mi = 0; mi < 2; mi++) {
        int r0 = mw * 32 + mi * 16 + (lane >> 2);
#pragma unroll
        for (int ni = 0; ni < 8; ni++) {
            int col = nw * 64 + ni * 8 + (lane & 3) * 2;
            smemC[r0 * 132 + col]           = acc[mi][ni][0];
            smemC[r0 * 132 + col + 1]       = acc[mi][ni][1];
            smemC[(r0 + 8) * 132 + col]     = acc[mi][ni][2];
            smemC[(r0 + 8) * 132 + col + 1] = acc[mi][ni][3];
        }
    }
    __syncthreads();

    if (mode <= 1) {
        float* dstT = (mode == 0) ? g_Qt : g_Kt;
        const int bB = m0 / LL;
        const int s0 = m0 - bB * LL;
#pragma unroll
        for (int i = 0; i < 16; i++) {
            int col = wid * 16 + i;
            float bi = s_bias[col];
            float4 o;
            o.x = smemC[(lane * 4 + 0) * 132 + col] + bi;
            o.y = smemC[(lane * 4 + 1) * 132 + col] + bi;
            o.z = smemC[(lane * 4 + 2) * 132 + col] + bi;
            o.w = smemC[(lane * 4 + 3) * 132 + col] + bi;
            *(float4*)&dstT[((size_t)bB * DD + n0 + col) * LL + s0 + lane * 4] = o;
        }
    } else {
        float* dstN = (mode == 2) ? g_V : Cext;
        const int row = tid >> 1;
        const int cb  = (tid & 1) * 64;
        const size_t rb = (size_t)(m0 + row) * DD + n0 + cb;
#pragma unroll
        for (int i = 0; i < 16; i++) {
            float4 v = *(float4*)&smemC[row * 132 + cb + i * 4];
            v.x += s_bias[cb + i * 4 + 0];
            v.y += s_bias[cb + i * 4 + 1];
            v.z += s_bias[cb + i * 4 + 2];
            v.w += s_bias[cb + i * 4 + 3];
            *(float4*)&dstN[rb + i * 4] = v;
        }
    }
}

// ---------------------------------------------------------------------------
// Twiddle init
// ---------------------------------------------------------------------------
__global__ void k_twiddle() {
    int j = blockIdx.x * blockDim.x + threadIdx.x;
    if (j < LL) {
        double a = -6.283185307179586476925286766559 * (double)j / (double)LL;
        g_tw[j] = make_float2((float)cos(a), (float)sin(a));
    }
}

// ---------------------------------------------------------------------------
// Mixed-radix (3 * 2^10) Stockham FFT in shared memory
// ---------------------------------------------------------------------------
__device__ __forceinline__ float2 cmul(float2 a, float2 b) {
    return make_float2(a.x * b.x - a.y * b.y, a.x * b.y + a.y * b.x);
}

template <int SGN>
__device__ float2* block_fft(float2* p0, float2* p1, int tid, int nt)
{
    {
        const float s0 = (SGN > 0) ? -0.86602540378443864676f
                                   :  0.86602540378443864676f;
        for (int p = tid; p < 1024; p += nt) {
            float2 a = p0[p], b = p0[p + 1024], c = p0[p + 2048];
            float ur = b.x + c.x, ui = b.y + c.y;
            float dr = b.x - c.x, di = b.y - c.y;
            float vr = a.x - 0.5f * ur, vi = a.y - 0.5f * ui;
            float wr = -s0 * di, wi = s0 * dr;
            float2 w1 = g_tw[p];       if (SGN < 0) w1.y = -w1.y;
            float2 w2 = g_tw[2 * p];   if (SGN < 0) w2.y = -w2.y;
            p1[3 * p]     = make_float2(a.x + ur, a.y + ui);
            p1[3 * p + 1] = cmul(make_float2(vr + wr, vi + wi), w1);
            p1[3 * p + 2] = cmul(make_float2(vr - wr, vi - wi), w2);
        }
    }
    __syncthreads();

    float2* px = p1;
    float2* py = p0;
    int n = 1024, s = 3;
    while (n > 1) {
        int m = n >> 1;
        int str = LL / n;
        for (int t = tid; t < 1536; t += nt) {
            int p = t / s;
            int q = t - p * s;
            float2 a = px[q + s * p];
            float2 b = px[q + s * (p + m)];
            float2 w = g_tw[p * str];  if (SGN < 0) w.y = -w.y;
            py[q + s * (2 * p)]     = make_float2(a.x + b.x, a.y + b.y);
            py[q + s * (2 * p + 1)] = cmul(make_float2(a.x - b.x, a.y - b.y), w);
        }
        __syncthreads();
        n = m; s <<= 1;
        float2* tp = px; px = py; py = tp;
    }
    return px;
}

// ---------------------------------------------------------------------------
// Forward FFT of q,k packed as z = q + i*k; write qhat * conj(khat)
// ---------------------------------------------------------------------------
__global__ __launch_bounds__(256) void k_fft()
{
    __shared__ __align__(16) float2 pool[2 * LL];
    float2* p0 = pool;
    float2* p1 = pool + LL;

    const int bc = blockIdx.x;
    const float* qr = g_Qt + (size_t)bc * LL;
    const float* kr = g_Kt + (size_t)bc * LL;
    const int tid = threadIdx.x;

    for (int i = tid; i < LL; i += 256) p0[i] = make_float2(qr[i], kr[i]);
    __syncthreads();

    float2* z = block_fft<1>(p0, p1, tid, 256);

    float2* P = g_P + (size_t)bc * NF;
    for (int f = tid; f < NF; f += 256) {
        float2 zf = z[f];
        int ridx = (f == 0) ? 0 : (LL - f);
        float2 zr = z[ridx];
        float qre = 0.5f * (zf.x + zr.x);
        float qim = 0.5f * (zf.y - zr.y);
        float dr = zf.x - zr.x;
        float di = zf.y + zr.y;
        float kre = 0.5f * di;
        float kim = -0.5f * dr;
        P[f] = make_float2(qre * kre + qim * kim, qim * kre - qre * kim);
    }
}

// ---------------------------------------------------------------------------
// Deterministic channel reduction: S[b,f] = sum_c P[b,c,f]
// ---------------------------------------------------------------------------
__global__ __launch_bounds__(256) void k_reduce()
{
    __shared__ float red[2][8][32];
    const int b    = blockIdx.y;
    const int lane = threadIdx.x & 31;
    const int cw   = threadIdx.x >> 5;
    const int f    = blockIdx.x * 32 + lane;

    float sr = 0.0f, si = 0.0f;
    if (f < NF) {
        for (int c = cw; c < DD; c += 8) {
            float2 v = g_P[((size_t)b * DD + c) * NF + f];
            sr += v.x; si += v.y;
        }
    }
    red[0][cw][lane] = sr;
    red[1][cw][lane] = si;
    __syncthreads();
    if (cw == 0 && f < NF) {
        float ar = 0.0f, ai = 0.0f;
#pragma unroll
        for (int w = 0; w < 8; w++) { ar += red[0][w][lane]; ai += red[1][w][lane]; }
        g_S[b * NF + f] = make_float2(ar, ai);
    }
}

// ---------------------------------------------------------------------------
// Per-batch inverse FFT -> mean_value, top-8 + softmax
// ---------------------------------------------------------------------------
__global__ __launch_bounds__(512) void k_ifft_topk()
{
    __shared__ __align__(16) float2 pool[2 * LL];
    float2* p0 = pool;
    float2* p1 = pool + LL;

    const int b = blockIdx.x;
    const int tid = threadIdx.x;
    const int nt = 512;

    for (int f = tid; f < LL; f += nt) {
        float2 v;
        if (f < NF) v = g_S[b * NF + f];
        else {
            float2 u = g_S[b * NF + (LL - f)];
            v = make_float2(u.x, -u.y);
        }
        p0[f] = v;
    }
    __syncthreads();

    float2* z = block_fft<-1>(p0, p1, tid, nt);

    float* meanArr = (float*)pool;
    float* redV    = meanArr + 3072;
    int*   redI    = (int*)(meanArr + 3584);

    const float scale = 1.0f / ((float)LL * (float)DD);
    for (int i = tid; i < LL; i += nt) meanArr[i] = z[i].x * scale;
    __syncthreads();

    float lw[TOPK];
    int   ld[TOPK];
    for (int k = 0; k < TOPK; k++) {
        float bv = -1e30f;
        int   bi = 0x7fffffff;
        for (int i = tid; i < LL; i += nt) {
            float v = meanArr[i];
            if (v > bv || (v == bv && i < bi)) { bv = v; bi = i; }
        }
        redV[tid] = bv; redI[tid] = bi;
        __syncthreads();
        for (int off = 256; off > 0; off >>= 1) {
            if (tid < off) {
                float v2 = redV[tid + off];
                int   i2 = redI[tid + off];
                if (v2 > redV[tid] || (v2 == redV[tid] && i2 < redI[tid])) {
                    redV[tid] = v2; redI[tid] = i2;
                }
            }
            __syncthreads();
        }
        if (tid == 0) {
            lw[k] = redV[0];
            ld[k] = redI[0];
            meanArr[redI[0]] = -1e30f;
        }
        __syncthreads();
    }

    if (tid == 0) {
        float mx = lw[0];
        for (int i = 1; i < TOPK; i++) mx = fmaxf(mx, lw[i]);
        float e[TOPK];
        float sum = 0.0f;
        for (int i = 0; i < TOPK; i++) { e[i] = expf(lw[i] - mx); sum += e[i]; }
        for (int i = 0; i < TOPK; i++) {
            g_w[b * TOPK + i] = e[i] / sum;
            g_d[b * TOPK + i] = ld[i];
        }
    }
}

// ---------------------------------------------------------------------------
// Time-delay aggregation, fused with the bf16 hi/lo split for the output GEMM
// (writes split region 0):
//   agg = sum_i w[b,i] * V[b][(s+d_i)%L][c]   ->  g_Ah/g_Al region 0
// grid (L, B), 256 threads.
// ---------------------------------------------------------------------------
__global__ __launch_bounds__(256) void k_agg()
{
    __shared__ float ws[TOPK];
    __shared__ int   ds[TOPK];
    const int s = blockIdx.x;
    const int b = blockIdx.y;
    const int tid = threadIdx.x;
    if (tid < TOPK) { ws[tid] = g_w[b * TOPK + tid]; ds[tid] = g_d[b * TOPK + tid]; }
    __syncthreads();

    const float* Vb = g_V + (size_t)b * LL * DD;
    const int c = tid * 4;
    float4 acc = make_float4(0.f, 0.f, 0.f, 0.f);
#pragma unroll
    for (int i = 0; i < TOPK; i++) {
        int j = s + ds[i];
        if (j >= LL) j -= LL;
        float4 v = *(const float4*)(Vb + (size_t)j * DD + c);
        float w = ws[i];
        acc.x += w * v.x; acc.y += w * v.y; acc.z += w * v.z; acc.w += w * v.w;
    }
    __nv_bfloat16 h0 = __float2bfloat16(acc.x), h1 = __float2bfloat16(acc.y);
    __nv_bfloat16 h2 = __float2bfloat16(acc.z), h3 = __float2bfloat16(acc.w);
    __nv_bfloat16 l0 = __float2bfloat16(acc.x - __bfloat162float(h0));
    __nv_bfloat16 l1 = __float2bfloat16(acc.y - __bfloat162float(h1));
    __nv_bfloat16 l2 = __float2bfloat16(acc.z - __bfloat162float(h2));
    __nv_bfloat16 l3 = __float2bfloat16(acc.w - __bfloat162float(h3));
    __nv_bfloat162 ha = __halves2bfloat162(h0, h1), hb = __halves2bfloat162(h2, h3);
    __nv_bfloat162 la = __halves2bfloat162(l0, l1), lb = __halves2bfloat162(l2, l3);
    size_t idx = ((size_t)b * LL + s) * DD + c;
    *(uint2*)(g_Ah + idx) = make_uint2(*(uint32_t*)&ha, *(uint32_t*)&hb);
    *(uint2*)(g_Al + idx) = make_uint2(*(uint32_t*)&la, *(uint32_t*)&lb);
}

// ---------------------------------------------------------------------------
// kernel_launch
// ---------------------------------------------------------------------------
extern "C" void kernel_launch(void* const* d_in, const int* in_sizes, int n_in,
                              void* d_out, int out_size)
{
    const float* queries = (const float*)d_in[0];
    const float* keys    = (const float*)d_in[1];
    const float* values  = (const float*)d_in[2];
    const float* Wq = (const float*)d_in[3];
    const float* bq = (const float*)d_in[4];
    const float* Wk = (const float*)d_in[5];
    const float* bk = (const float*)d_in[6];
    const float* Wv = (const float*)d_in[7];
    const float* bv = (const float*)d_in[8];
    const float* Wo = (const float*)d_in[9];
    const float* bo = (const float*)d_in[10];
    float* Out = (float*)d_out;

    (void)in_sizes; (void)n_in; (void)out_size;

    const int dynC = NSTG * BUF_SZ;   // 98304 (>= epilogue's 67584)
    cudaFuncSetAttribute(k_gemm, cudaFuncAttributeMaxDynamicSharedMemorySize, dynC);

    k_twiddle<<<(LL + 255) / 256, 256>>>();
    k_wconv<<<dim3(32, 32, 4), dim3(32, 8)>>>(Wq, Wk, Wv, Wo);

    const int nsplit = (int)((size_t)MTOT * DD / 1024);   // 24576 blocks
    k_asplit3<<<dim3(nsplit, 3), 256>>>((const float4*)queries,
                                        (const float4*)keys,
                                        (const float4*)values);

    dim3 gg(DD / 128, MTOT / 128);    // (8, 192)
    k_gemm<<<gg, 256, dynC>>>(0, 0, bq, Out, 0);
    k_gemm<<<gg, 256, dynC>>>(1, 1, bk, Out, 1);
    k_gemm<<<gg, 256, dynC>>>(2, 2, bv, Out, 2);

    k_fft<<<BB * DD, 256>>>();
    k_reduce<<<dim3((NF + 31) / 32, BB), 256>>>();
    k_ifft_topk<<<BB, 512>>>();
    k_agg<<<dim3(LL, BB), 256>>>();

    k_gemm<<<gg, 256, dynC>>>(0, 3, bo, Out, 3);
}

// round 5
// speedup vs baseline: 1.6547x; 1.0434x over previous
#include <cuda_runtime.h>
#include <cuda_bf16.h>
#include <math.h>
#include <stdint.h>

// Problem constants
#define BB   8
#define LL   3072
#define DD   1024
#define TOPK 8
#define NF   1537          // LL/2 + 1

#define MTOT (BB * LL)     // 24576

// ---------------------------------------------------------------------------
// Static device scratch
// ---------------------------------------------------------------------------
__device__ float  g_Qt[(size_t)BB * DD * LL];     // q projected, [B][D][L]
__device__ float  g_Kt[(size_t)BB * DD * LL];     // k projected, [B][D][L]
__device__ float  g_V [(size_t)BB * LL * DD];     // v projected, [B][L][D]
__device__ float2 g_P[(size_t)BB * DD * NF];
__device__ float2 g_S[BB * NF];
__device__ float2 g_tw[LL];
__device__ float  g_w[BB * TOPK];
__device__ int    g_d[BB * TOPK];
// bf16 hi/lo split A operands: 3 regions (Q,K,V); region 0 reused by k_agg
__device__ __align__(16) __nv_bfloat16 g_Ah[(size_t)3 * MTOT * DD];
__device__ __align__(16) __nv_bfloat16 g_Al[(size_t)3 * MTOT * DD];
__device__ __align__(16) __nv_bfloat16 g_Bh[(size_t)4 * DD * DD];  // Bw[n][k]=W[k][n]
__device__ __align__(16) __nv_bfloat16 g_Bl[(size_t)4 * DD * DD];

// ---------------------------------------------------------------------------
// PTX helpers (all base-ISA; no 'a'-suffix features)
// ---------------------------------------------------------------------------
__device__ __forceinline__ uint32_t smem_u32(const void* p) {
    uint32_t a;
    asm("{ .reg .u64 t; cvta.to.shared.u64 t, %1; cvt.u32.u64 %0, t; }"
        : "=r"(a) : "l"(p));
    return a;
}
__device__ __forceinline__ void cp16(uint32_t s, const void* g) {
    asm volatile("cp.async.cg.shared.global [%0], [%1], 16;" :: "r"(s), "l"(g));
}
__device__ __forceinline__ void cp_commit() {
    asm volatile("cp.async.commit_group;");
}
// Not volatile — pure data ops; lets the scheduler hoist/interleave.
__device__ __forceinline__ void ldmx4(uint32_t* r, uint32_t a) {
    asm("ldmatrix.sync.aligned.m8n8.x4.shared.b16 {%0,%1,%2,%3}, [%4];"
        : "=r"(r[0]), "=r"(r[1]), "=r"(r[2]), "=r"(r[3]) : "r"(a));
}
__device__ __forceinline__ void mma16816(float* d, const uint32_t* a,
                                         uint32_t b0, uint32_t b1) {
    asm("mma.sync.aligned.m16n8k16.row.col.f32.bf16.bf16.f32 "
        "{%0,%1,%2,%3}, {%4,%5,%6,%7}, {%8,%9}, {%0,%1,%2,%3};"
        : "+f"(d[0]), "+f"(d[1]), "+f"(d[2]), "+f"(d[3])
        : "r"(a[0]), "r"(a[1]), "r"(a[2]), "r"(a[3]), "r"(b0), "r"(b1));
}

// ---------------------------------------------------------------------------
// Weight transpose + bf16 hi/lo split:  Bw[n][k] = split(W[k][n])
// ---------------------------------------------------------------------------
__global__ void k_wconv(const float* __restrict__ W0, const float* __restrict__ W1,
                        const float* __restrict__ W2, const float* __restrict__ W3)
{
    __shared__ float t[32][33];
    int z = blockIdx.z;
    const float* W = (z == 0) ? W0 : (z == 1) ? W1 : (z == 2) ? W2 : W3;
    __nv_bfloat16* Bh = g_Bh + (size_t)z * DD * DD;
    __nv_bfloat16* Bl = g_Bl + (size_t)z * DD * DD;
    int n0 = blockIdx.x * 32, k0 = blockIdx.y * 32;
    int tx = threadIdx.x, ty = threadIdx.y;
#pragma unroll
    for (int j = 0; j < 32; j += 8)
        t[ty + j][tx] = W[(size_t)(k0 + ty + j) * DD + n0 + tx];
    __syncthreads();
#pragma unroll
    for (int j = 0; j < 32; j += 8) {
        float x = t[tx][ty + j];
        __nv_bfloat16 h = __float2bfloat16(x);
        float lo = x - __bfloat162float(h);
        Bh[(size_t)(n0 + ty + j) * DD + k0 + tx] = h;
        Bl[(size_t)(n0 + ty + j) * DD + k0 + tx] = __float2bfloat16(lo);
    }
}

// ---------------------------------------------------------------------------
// A split for Q,K,V in one launch: fp32 -> bf16 hi/lo into region blockIdx.y
// ---------------------------------------------------------------------------
__global__ __launch_bounds__(256) void k_asplit3(
    const float4* __restrict__ X0, const float4* __restrict__ X1,
    const float4* __restrict__ X2)
{
    const int reg = blockIdx.y;
    const float4* X = (reg == 0) ? X0 : (reg == 1) ? X1 : X2;
    size_t i = (size_t)blockIdx.x * 256 + threadIdx.x;
    float4 v = X[i];
    __nv_bfloat16 h0 = __float2bfloat16(v.x), h1 = __float2bfloat16(v.y);
    __nv_bfloat16 h2 = __float2bfloat16(v.z), h3 = __float2bfloat16(v.w);
    __nv_bfloat16 l0 = __float2bfloat16(v.x - __bfloat162float(h0));
    __nv_bfloat16 l1 = __float2bfloat16(v.y - __bfloat162float(h1));
    __nv_bfloat16 l2 = __float2bfloat16(v.z - __bfloat162float(h2));
    __nv_bfloat16 l3 = __float2bfloat16(v.w - __bfloat162float(h3));
    __nv_bfloat162 ha = __halves2bfloat162(h0, h1), hb = __halves2bfloat162(h2, h3);
    __nv_bfloat162 la = __halves2bfloat162(l0, l1), lb = __halves2bfloat162(l2, l3);
    size_t o = (size_t)reg * (MTOT * DD / 4) + i;
    ((uint2*)g_Ah)[o] = make_uint2(*(uint32_t*)&ha, *(uint32_t*)&hb);
    ((uint2*)g_Al)[o] = make_uint2(*(uint32_t*)&la, *(uint32_t*)&lb);
}

// ---------------------------------------------------------------------------
// Tensor-core GEMM (mma.sync bf16, 3-term split):
//   C[m][n] = sum_k (Ah+Al)[m][k] * (Bh+Bl)[n][k]  + bias[n]   (AlBl dropped)
// CTA tile 128x128, k-chunk 32, cp.async triple buffer, 8 warps (4m x 2n),
// warp tile 32x64. B n16-groups processed in PAIRS with term-major issue:
// same-accumulator reuse distance = 8 (64 cyc at rt=8) to cover HMMA latency.
// zsel: derive (areg,widx,mode) from blockIdx.z (fused Q/K/V launch).
// modes: 0/1 -> transposed g_Qt/g_Kt, 2 -> g_V natural, 3 -> Cext natural.
// ---------------------------------------------------------------------------
#define KC 32
#define NC (DD / KC)       // 32 chunks
#define OFF_B 16384        // B region offset within a 32KB buffer
#define BUF_SZ 32768
#define NSTG 3

__global__ __launch_bounds__(256, 2)
void k_gemm(int areg, int widx, const float* __restrict__ bias0,
            const float* __restrict__ bias1, const float* __restrict__ bias2,
            float* __restrict__ Cext, int mode, int zsel)
{
    extern __shared__ __align__(16) char smem[];
    __shared__ float s_bias[128];

    if (zsel) { areg = blockIdx.z; widx = blockIdx.z; mode = blockIdx.z; }
    const float* bias = (widx == 1) ? bias1 : (widx == 2) ? bias2 : bias0;

    const int tid  = threadIdx.x;
    const int wid  = tid >> 5;
    const int lane = tid & 31;
    const int n0 = blockIdx.x * 128;
    const int m0 = blockIdx.y * 128;
    const int mw = wid >> 1;      // 0..3
    const int nw = wid & 1;       // 0..1

    const __nv_bfloat16* Ah = g_Ah + (size_t)areg * MTOT * DD;
    const __nv_bfloat16* Al = g_Al + (size_t)areg * MTOT * DD;
    const __nv_bfloat16* Bh = g_Bh + (size_t)widx * DD * DD;
    const __nv_bfloat16* Bl = g_Bl + (size_t)widx * DD * DD;

    if (tid < 128) s_bias[tid] = bias[n0 + tid];

    const uint32_t sbase = smem_u32(smem);

    float acc[2][8][4];
#pragma unroll
    for (int i = 0; i < 2; i++)
#pragma unroll
        for (int j = 0; j < 8; j++)
#pragma unroll
            for (int q = 0; q < 4; q++) acc[i][j][q] = 0.0f;

    // ---- async load of one chunk into buffer b ----
    auto load_chunk = [&](int c, int b) {
        uint32_t sb = sbase + b * BUF_SZ;
        const int k0 = c * KC;
#pragma unroll
        for (int u = 0; u < 4; u++) {
            int idx  = tid * 4 + u;          // 0..1023
            int row  = idx >> 3;
            int seg8 = idx & 7;
            int lo   = seg8 >> 2;
            int seg  = seg8 & 3;
            uint32_t so = (uint32_t)(row * 128 + ((seg8 ^ (row & 7)) * 16));
            const __nv_bfloat16* gA = (lo ? Al : Ah)
                + (size_t)(m0 + row) * DD + k0 + seg * 8;
            cp16(sb + so, gA);
            const __nv_bfloat16* gB = (lo ? Bl : Bh)
                + (size_t)(n0 + row) * DD + k0 + seg * 8;
            cp16(sb + OFF_B + so, gB);
        }
        cp_commit();
    };

    load_chunk(0, 0);
    load_chunk(1, 1);

    int bufc = 0;   // c % 3
    for (int c = 0; c < NC; c++) {
        if (c + 2 < NC) {
            int b2 = bufc + 2; if (b2 >= NSTG) b2 -= NSTG;
            load_chunk(c + 2, b2);
            asm volatile("cp.async.wait_group 2;");
        } else if (c + 1 < NC) {
            asm volatile("cp.async.wait_group 1;");
        } else {
            asm volatile("cp.async.wait_group 0;");
        }
        __syncthreads();

        const uint32_t bufu = sbase + bufc * BUF_SZ;

#pragma unroll
        for (int ks = 0; ks < 2; ks++) {
            // A fragments (hi & lo) for both m16 tiles
            uint32_t ah[2][4], al[2][4];
            const int arow0 = mw * 32 + (lane & 7) + ((lane >> 3) & 1) * 8;
            const int sega  = ks * 2 + (lane >> 4);
#pragma unroll
            for (int mi = 0; mi < 2; mi++) {
                int row = arow0 + mi * 16;
                uint32_t ra = bufu + row * 128;
                ldmx4(ah[mi], ra + ((sega       ^ (row & 7)) * 16));
                ldmx4(al[mi], ra + (((sega + 4) ^ (row & 7)) * 16));
            }
            const int nrow0 = nw * 64 + ((lane >> 4) & 1) * 8 + (lane & 7);
            const int segb  = ks * 2 + ((lane >> 3) & 1);
            // Process n16 groups in pairs: 4 B fragments live, then 24 MMAs
            // term-major over 8 distinct accumulators (reuse distance 8).
#pragma unroll
            for (int gp = 0; gp < 2; gp++) {
                uint32_t bh[2][4], bl[2][4];
#pragma unroll
                for (int gg = 0; gg < 2; gg++) {
                    int nrow = nrow0 + (gp * 2 + gg) * 16;
                    uint32_t rb = bufu + OFF_B + nrow * 128;
                    ldmx4(bh[gg], rb + ((segb       ^ (nrow & 7)) * 16));
                    ldmx4(bl[gg], rb + (((segb + 4) ^ (nrow & 7)) * 16));
                }
                // term Ah*Bh : 8 independent accumulators
#pragma unroll
                for (int gg = 0; gg < 2; gg++)
#pragma unroll
                    for (int half = 0; half < 2; half++)
#pragma unroll
                        for (int mi = 0; mi < 2; mi++)
                            mma16816(acc[mi][(gp * 2 + gg) * 2 + half], ah[mi],
                                     bh[gg][half * 2], bh[gg][half * 2 + 1]);
                // term Ah*Bl
#pragma unroll
                for (int gg = 0; gg < 2; gg++)
#pragma unroll
                    for (int half = 0; half < 2; half++)
#pragma unroll
                        for (int mi = 0; mi < 2; mi++)
                            mma16816(acc[mi][(gp * 2 + gg) * 2 + half], ah[mi],
                                     bl[gg][half * 2], bl[gg][half * 2 + 1]);
                // term Al*Bh
#pragma unroll
                for (int gg = 0; gg < 2; gg++)
#pragma unroll
                    for (int half = 0; half < 2; half++)
#pragma unroll
                        for (int mi = 0; mi < 2; mi++)
                            mma16816(acc[mi][(gp * 2 + gg) * 2 + half], al[mi],
                                     bh[gg][half * 2], bh[gg][half * 2 + 1]);
            }
        }
        __syncthreads();
        bufc = (bufc + 1 == NSTG) ? 0 : bufc + 1;
    }

    // ---- Epilogue: stage C tile (128 x 132 fp32) in smem, write coalesced ----
    float* smemC = (float*)smem;
#pragma unroll
    for (int mi = 0; mi < 2; mi++) {
        int r0 = mw * 32 + mi * 16 + (lane >> 2);
#pragma unroll
        for (int ni = 0; ni < 8; ni++) {
            int col = nw * 64 + ni * 8 + (lane & 3) * 2;
            smemC[r0 * 132 + col]           = acc[mi][ni][0];
            smemC[r0 * 132 + col + 1]       = acc[mi][ni][1];
            smemC[(r0 + 8) * 132 + col]     = acc[mi][ni][2];
            smemC[(r0 + 8) * 132 + col + 1] = acc[mi][ni][3];
        }
    }
    __syncthreads();

    if (mode <= 1) {
        float* dstT = (mode == 0) ? g_Qt : g_Kt;
        const int bB = m0 / LL;
        const int s0 = m0 - bB * LL;
#pragma unroll
        for (int i = 0; i < 16; i++) {
            int col = wid * 16 + i;
            float bi = s_bias[col];
            float4 o;
            o.x = smemC[(lane * 4 + 0) * 132 + col] + bi;
            o.y = smemC[(lane * 4 + 1) * 132 + col] + bi;
            o.z = smemC[(lane * 4 + 2) * 132 + col] + bi;
            o.w = smemC[(lane * 4 + 3) * 132 + col] + bi;
            *(float4*)&dstT[((size_t)bB * DD + n0 + col) * LL + s0 + lane * 4] = o;
        }
    } else {
        float* dstN = (mode == 2) ? g_V : Cext;
        const int row = tid >> 1;
        const int cb  = (tid & 1) * 64;
        const size_t rb = (size_t)(m0 + row) * DD + n0 + cb;
#pragma unroll
        for (int i = 0; i < 16; i++) {
            float4 v = *(float4*)&smemC[row * 132 + cb + i * 4];
            v.x += s_bias[cb + i * 4 + 0];
            v.y += s_bias[cb + i * 4 + 1];
            v.z += s_bias[cb + i * 4 + 2];
            v.w += s_bias[cb + i * 4 + 3];
            *(float4*)&dstN[rb + i * 4] = v;
        }
    }
}

// ---------------------------------------------------------------------------
// Twiddle init
// ---------------------------------------------------------------------------
__global__ void k_twiddle() {
    int j = blockIdx.x * blockDim.x + threadIdx.x;
    if (j < LL) {
        double a = -6.283185307179586476925286766559 * (double)j / (double)LL;
        g_tw[j] = make_float2((float)cos(a), (float)sin(a));
    }
}

// ---------------------------------------------------------------------------
// Mixed-radix (3 * 2^10) Stockham FFT in shared memory
// ---------------------------------------------------------------------------
__device__ __forceinline__ float2 cmul(float2 a, float2 b) {
    return make_float2(a.x * b.x - a.y * b.y, a.x * b.y + a.y * b.x);
}

template <int SGN>
__device__ float2* block_fft(float2* p0, float2* p1, int tid, int nt)
{
    {
        const float s0 = (SGN > 0) ? -0.86602540378443864676f
                                   :  0.86602540378443864676f;
        for (int p = tid; p < 1024; p += nt) {
            float2 a = p0[p], b = p0[p + 1024], c = p0[p + 2048];
            float ur = b.x + c.x, ui = b.y + c.y;
            float dr = b.x - c.x, di = b.y - c.y;
            float vr = a.x - 0.5f * ur, vi = a.y - 0.5f * ui;
            float wr = -s0 * di, wi = s0 * dr;
            float2 w1 = g_tw[p];       if (SGN < 0) w1.y = -w1.y;
            float2 w2 = g_tw[2 * p];   if (SGN < 0) w2.y = -w2.y;
            p1[3 * p]     = make_float2(a.x + ur, a.y + ui);
            p1[3 * p + 1] = cmul(make_float2(vr + wr, vi + wi), w1);
            p1[3 * p + 2] = cmul(make_float2(vr - wr, vi - wi), w2);
        }
    }
    __syncthreads();

    float2* px = p1;
    float2* py = p0;
    int n = 1024, s = 3;
    while (n > 1) {
        int m = n >> 1;
        int str = LL / n;
        for (int t = tid; t < 1536; t += nt) {
            int p = t / s;
            int q = t - p * s;
            float2 a = px[q + s * p];
            float2 b = px[q + s * (p + m)];
            float2 w = g_tw[p * str];  if (SGN < 0) w.y = -w.y;
            py[q + s * (2 * p)]     = make_float2(a.x + b.x, a.y + b.y);
            py[q + s * (2 * p + 1)] = cmul(make_float2(a.x - b.x, a.y - b.y), w);
        }
        __syncthreads();
        n = m; s <<= 1;
        float2* tp = px; px = py; py = tp;
    }
    return px;
}

// ---------------------------------------------------------------------------
// Forward FFT of q,k packed as z = q + i*k; write qhat * conj(khat)
// ---------------------------------------------------------------------------
__global__ __launch_bounds__(256) void k_fft()
{
    __shared__ __align__(16) float2 pool[2 * LL];
    float2* p0 = pool;
    float2* p1 = pool + LL;

    const int bc = blockIdx.x;
    const float* qr = g_Qt + (size_t)bc * LL;
    const float* kr = g_Kt + (size_t)bc * LL;
    const int tid = threadIdx.x;

    for (int i = tid; i < LL; i += 256) p0[i] = make_float2(qr[i], kr[i]);
    __syncthreads();

    float2* z = block_fft<1>(p0, p1, tid, 256);

    float2* P = g_P + (size_t)bc * NF;
    for (int f = tid; f < NF; f += 256) {
        float2 zf = z[f];
        int ridx = (f == 0) ? 0 : (LL - f);
        float2 zr = z[ridx];
        float qre = 0.5f * (zf.x + zr.x);
        float qim = 0.5f * (zf.y - zr.y);
        float dr = zf.x - zr.x;
        float di = zf.y + zr.y;
        float kre = 0.5f * di;
        float kim = -0.5f * dr;
        P[f] = make_float2(qre * kre + qim * kim, qim * kre - qre * kim);
    }
}

// ---------------------------------------------------------------------------
// Deterministic channel reduction: S[b,f] = sum_c P[b,c,f]
// ---------------------------------------------------------------------------
__global__ __launch_bounds__(256) void k_reduce()
{
    __shared__ float red[2][8][32];
    const int b    = blockIdx.y;
    const int lane = threadIdx.x & 31;
    const int cw   = threadIdx.x >> 5;
    const int f    = blockIdx.x * 32 + lane;

    float sr = 0.0f, si = 0.0f;
    if (f < NF) {
        for (int c = cw; c < DD; c += 8) {
            float2 v = g_P[((size_t)b * DD + c) * NF + f];
            sr += v.x; si += v.y;
        }
    }
    red[0][cw][lane] = sr;
    red[1][cw][lane] = si;
    __syncthreads();
    if (cw == 0 && f < NF) {
        float ar = 0.0f, ai = 0.0f;
#pragma unroll
        for (int w = 0; w < 8; w++) { ar += red[0][w][lane]; ai += red[1][w][lane]; }
        g_S[b * NF + f] = make_float2(ar, ai);
    }
}

// ---------------------------------------------------------------------------
// Per-batch inverse FFT -> mean_value, top-8 + softmax
// ---------------------------------------------------------------------------
__global__ __launch_bounds__(512) void k_ifft_topk()
{
    __shared__ __align__(16) float2 pool[2 * LL];
    float2* p0 = pool;
    float2* p1 = pool + LL;

    const int b = blockIdx.x;
    const int tid = threadIdx.x;
    const int nt = 512;

    for (int f = tid; f < LL; f += nt) {
        float2 v;
        if (f < NF) v = g_S[b * NF + f];
        else {
            float2 u = g_S[b * NF + (LL - f)];
            v = make_float2(u.x, -u.y);
        }
        p0[f] = v;
    }
    __syncthreads();

    float2* z = block_fft<-1>(p0, p1, tid, nt);

    float* meanArr = (float*)pool;
    float* redV    = meanArr + 3072;
    int*   redI    = (int*)(meanArr + 3584);

    const float scale = 1.0f / ((float)LL * (float)DD);
    for (int i = tid; i < LL; i += nt) meanArr[i] = z[i].x * scale;
    __syncthreads();

    float lw[TOPK];
    int   ld[TOPK];
    for (int k = 0; k < TOPK; k++) {
        float bv = -1e30f;
        int   bi = 0x7fffffff;
        for (int i = tid; i < LL; i += nt) {
            float v = meanArr[i];
            if (v > bv || (v == bv && i < bi)) { bv = v; bi = i; }
        }
        redV[tid] = bv; redI[tid] = bi;
        __syncthreads();
        for (int off = 256; off > 0; off >>= 1) {
            if (tid < off) {
                float v2 = redV[tid + off];
                int   i2 = redI[tid + off];
                if (v2 > redV[tid] || (v2 == redV[tid] && i2 < redI[tid])) {
                    redV[tid] = v2; redI[tid] = i2;
                }
            }
            __syncthreads();
        }
        if (tid == 0) {
            lw[k] = redV[0];
            ld[k] = redI[0];
            meanArr[redI[0]] = -1e30f;
        }
        __syncthreads();
    }

    if (tid == 0) {
        float mx = lw[0];
        for (int i = 1; i < TOPK; i++) mx = fmaxf(mx, lw[i]);
        float e[TOPK];
        float sum = 0.0f;
        for (int i = 0; i < TOPK; i++) { e[i] = expf(lw[i] - mx); sum += e[i]; }
        for (int i = 0; i < TOPK; i++) {
            g_w[b * TOPK + i] = e[i] / sum;
            g_d[b * TOPK + i] = ld[i];
        }
    }
}

// ---------------------------------------------------------------------------
// Time-delay aggregation, fused with the bf16 hi/lo split (writes region 0)
// ---------------------------------------------------------------------------
__global__ __launch_bounds__(256) void k_agg()
{
    __shared__ float ws[TOPK];
    __shared__ int   ds[TOPK];
    const int s = blockIdx.x;
    const int b = blockIdx.y;
    const int tid = threadIdx.x;
    if (tid < TOPK) { ws[tid] = g_w[b * TOPK + tid]; ds[tid] = g_d[b * TOPK + tid]; }
    __syncthreads();

    const float* Vb = g_V + (size_t)b * LL * DD;
    const int c = tid * 4;
    float4 acc = make_float4(0.f, 0.f, 0.f, 0.f);
#pragma unroll
    for (int i = 0; i < TOPK; i++) {
        int j = s + ds[i];
        if (j >= LL) j -= LL;
        float4 v = *(const float4*)(Vb + (size_t)j * DD + c);
        float w = ws[i];
        acc.x += w * v.x; acc.y += w * v.y; acc.z += w * v.z; acc.w += w * v.w;
    }
    __nv_bfloat16 h0 = __float2bfloat16(acc.x), h1 = __float2bfloat16(acc.y);
    __nv_bfloat16 h2 = __float2bfloat16(acc.z), h3 = __float2bfloat16(acc.w);
    __nv_bfloat16 l0 = __float2bfloat16(acc.x - __bfloat162float(h0));
    __nv_bfloat16 l1 = __float2bfloat16(acc.y - __bfloat162float(h1));
    __nv_bfloat16 l2 = __float2bfloat16(acc.z - __bfloat162float(h2));
    __nv_bfloat16 l3 = __float2bfloat16(acc.w - __bfloat162float(h3));
    __nv_bfloat162 ha = __halves2bfloat162(h0, h1), hb = __halves2bfloat162(h2, h3);
    __nv_bfloat162 la = __halves2bfloat162(l0, l1), lb = __halves2bfloat162(l2, l3);
    size_t idx = ((size_t)b * LL + s) * DD + c;
    *(uint2*)(g_Ah + idx) = make_uint2(*(uint32_t*)&ha, *(uint32_t*)&hb);
    *(uint2*)(g_Al + idx) = make_uint2(*(uint32_t*)&la, *(uint32_t*)&lb);
}

// ---------------------------------------------------------------------------
// kernel_launch
// ---------------------------------------------------------------------------
extern "C" void kernel_launch(void* const* d_in, const int* in_sizes, int n_in,
                              void* d_out, int out_size)
{
    const float* queries = (const float*)d_in[0];
    const float* keys    = (const float*)d_in[1];
    const float* values  = (const float*)d_in[2];
    const float* Wq = (const float*)d_in[3];
    const float* bq = (const float*)d_in[4];
    const float* Wk = (const float*)d_in[5];
    const float* bk = (const float*)d_in[6];
    const float* Wv = (const float*)d_in[7];
    const float* bv = (const float*)d_in[8];
    const float* Wo = (const float*)d_in[9];
    const float* bo = (const float*)d_in[10];
    float* Out = (float*)d_out;

    (void)in_sizes; (void)n_in; (void)out_size;

    const int dynC = NSTG * BUF_SZ;   // 98304 (>= epilogue's 67584)
    cudaFuncSetAttribute(k_gemm, cudaFuncAttributeMaxDynamicSharedMemorySize, dynC);

    k_twiddle<<<(LL + 255) / 256, 256>>>();
    k_wconv<<<dim3(32, 32, 4), dim3(32, 8)>>>(Wq, Wk, Wv, Wo);

    const int nsplit = (int)((size_t)MTOT * DD / 1024);   // 24576 blocks
    k_asplit3<<<dim3(nsplit, 3), 256>>>((const float4*)queries,
                                        (const float4*)keys,
                                        (const float4*)values);

    // fused Q/K/V projection GEMMs (z selects operand set + output mode)
    k_gemm<<<dim3(DD / 128, MTOT / 128, 3), 256, dynC>>>(
        0, 0, bq, bk, bv, Out, 0, 1);

    k_fft<<<BB * DD, 256>>>();
    k_reduce<<<dim3((NF + 31) / 32, BB), 256>>>();
    k_ifft_topk<<<BB, 512>>>();
    k_agg<<<dim3(LL, BB), 256>>>();

    k_gemm<<<dim3(DD / 128, MTOT / 128, 1), 256, dynC>>>(
        0, 3, bo, bo, bo, Out, 3, 0);
}